// round 1
// baseline (speedup 1.0000x reference)
#include <cuda_runtime.h>
#include <cuda_bf16.h>
#include <cstdint>

#define BATCH 256
#define N_GENES 8192
#define WM 4
#define HID (N_GENES * WM)       // 32768
#define N_TF 1024
#define GPT 64
#define EDGES3 (GPT * WM)        // 256
#define EPS 1e-5f
#define GENES_PER_BLOCK 32

// Scratch: layer-2 output stored TRANSPOSED: hT[col * BATCH + b]
__device__ float g_hT[HID * BATCH];

__device__ __forceinline__ float warp_sum(float v) {
#pragma unroll
    for (int o = 16; o; o >>= 1) v += __shfl_xor_sync(0xffffffffu, v, o);
    return v;
}

// Fused: layer1 (fan_in 1) -> relu -> BN -> layer2 (4x4 per-gene) -> relu -> BN
// One warp handles one gene (4 columns x 256 batch rows; 8 rows per lane).
__global__ __launch_bounds__(256) void k_layers12(
    const float* __restrict__ x,    // [BATCH, N_GENES] row-major
    const float* __restrict__ w1, const float* __restrict__ b1,
    const float* __restrict__ w2, const float* __restrict__ b2)
{
    __shared__ float sx[BATCH][GENES_PER_BLOCK + 1];  // +1 pad: conflict-free column reads

    const int g0 = blockIdx.x * GENES_PER_BLOCK;
    const int t = threadIdx.x;
    const int warp = t >> 5;
    const int lane = t & 31;

    // Coalesced tile load: x[0:256, g0:g0+32]
#pragma unroll 8
    for (int i = 0; i < 32; i++) {
        int r = i * 8 + warp;
        sx[r][lane] = x[r * N_GENES + g0 + lane];
    }
    __syncthreads();

#pragma unroll 1
    for (int gi = warp; gi < GENES_PER_BLOCK; gi += 8) {
        const int g = g0 + gi;

        float w1v[4], b1v[4], b2v[4], w2v[16];
#pragma unroll
        for (int j = 0; j < 4; j++) {
            w1v[j] = w1[4 * g + j];
            b1v[j] = b1[4 * g + j];
            b2v[j] = b2[4 * g + j];
        }
#pragma unroll
        for (int e = 0; e < 16; e++) w2v[e] = w2[16 * g + e];

        // layer1 + relu ; lane handles batches b = lane + 32k
        float h1[8][4];
#pragma unroll
        for (int k = 0; k < 8; k++) {
            float xv = sx[lane + 32 * k][gi];
#pragma unroll
            for (int j = 0; j < 4; j++)
                h1[k][j] = fmaxf(fmaf(w1v[j], xv, b1v[j]), 0.0f);
        }

        // BatchNorm per column j (two-pass over 256 values in the warp)
#pragma unroll
        for (int j = 0; j < 4; j++) {
            float s = 0.f;
#pragma unroll
            for (int k = 0; k < 8; k++) s += h1[k][j];
            float m = warp_sum(s) * (1.0f / BATCH);
            float vs = 0.f;
#pragma unroll
            for (int k = 0; k < 8; k++) { float d = h1[k][j] - m; vs += d * d; }
            float inv = rsqrtf(warp_sum(vs) * (1.0f / BATCH) + EPS);
#pragma unroll
            for (int k = 0; k < 8; k++) h1[k][j] = (h1[k][j] - m) * inv;
        }

        // layer2: h2[k][i] = relu(b2[i] + sum_j w2[16g+4i+j] * h1[k][j])
        float h2[8][4];
#pragma unroll
        for (int k = 0; k < 8; k++) {
#pragma unroll
            for (int i = 0; i < 4; i++) {
                float acc = b2v[i];
#pragma unroll
                for (int j = 0; j < 4; j++) acc = fmaf(w2v[4 * i + j], h1[k][j], acc);
                h2[k][i] = fmaxf(acc, 0.0f);
            }
        }

        // BatchNorm per column i, then transposed coalesced store
#pragma unroll
        for (int i = 0; i < 4; i++) {
            float s = 0.f;
#pragma unroll
            for (int k = 0; k < 8; k++) s += h2[k][i];
            float m = warp_sum(s) * (1.0f / BATCH);
            float vs = 0.f;
#pragma unroll
            for (int k = 0; k < 8; k++) { float d = h2[k][i] - m; vs += d * d; }
            float inv = rsqrtf(warp_sum(vs) * (1.0f / BATCH) + EPS);
            float* dst = &g_hT[(4 * g + i) * BATCH];
#pragma unroll
            for (int k = 0; k < 8; k++)
                dst[lane + 32 * k] = (h2[k][i] - m) * inv;
        }
    }
}

// layer3 gather + final BN. One block per TF, thread = batch index.
__global__ __launch_bounds__(256) void k_layer3(
    const float* __restrict__ w3, const float* __restrict__ b3,
    const int* __restrict__ cols3,
    float* __restrict__ out)   // [BATCH, N_TF]
{
    const int tf = blockIdx.x;
    const int b = threadIdx.x;
    const int warp = b >> 5;
    const int lane = b & 31;

    __shared__ float sw[EDGES3];
    __shared__ int sc[EDGES3];
    __shared__ float sred[8];

    sw[b] = w3[tf * EDGES3 + b];
    sc[b] = cols3[tf * EDGES3 + b] * BATCH;
    __syncthreads();

    float acc = b3[tf];
#pragma unroll 8
    for (int e = 0; e < EDGES3; e++) {
        acc = fmaf(sw[e], g_hT[sc[e] + b], acc);
    }

    // BN over the 256 batch values of this TF column (two-pass)
    float s = warp_sum(acc);
    if (lane == 0) sred[warp] = s;
    __syncthreads();
    float m = 0.f;
#pragma unroll
    for (int i = 0; i < 8; i++) m += sred[i];
    m *= (1.0f / BATCH);
    __syncthreads();

    float d = acc - m;
    float v = warp_sum(d * d);
    if (lane == 0) sred[warp] = v;
    __syncthreads();
    float var = 0.f;
#pragma unroll
    for (int i = 0; i < 8; i++) var += sred[i];
    var *= (1.0f / BATCH);

    out[b * N_TF + tf] = d * rsqrtf(var + EPS);
}

extern "C" void kernel_launch(void* const* d_in, const int* in_sizes, int n_in,
                              void* d_out, int out_size)
{
    const float* x  = (const float*)d_in[0];
    const float* w1 = (const float*)d_in[1];
    const float* b1 = (const float*)d_in[2];
    const float* w2 = (const float*)d_in[3];
    const float* b2 = (const float*)d_in[4];
    const float* w3 = (const float*)d_in[5];
    const float* b3 = (const float*)d_in[6];
    const int* cols3 = (const int*)d_in[12];
    float* out = (float*)d_out;

    k_layers12<<<N_GENES / GENES_PER_BLOCK, 256>>>(x, w1, b1, w2, b2);
    k_layer3<<<N_TF, 256>>>(w3, b3, cols3, out);
}

// round 2
// speedup vs baseline: 1.2178x; 1.2178x over previous
#include <cuda_runtime.h>
#include <cuda_fp16.h>
#include <cstdint>

#define BATCH 256
#define N_GENES 8192
#define WM 4
#define HID (N_GENES * WM)       // 32768
#define N_TF 1024
#define GPT 64
#define EDGES3 (GPT * WM)        // 256
#define EPS 1e-5f
#define GENES_PER_BLOCK 8

// Scratch: layer-2 output stored TRANSPOSED in fp16: hT[col * BATCH + b]
__device__ __half g_hT[HID * BATCH];

__device__ __forceinline__ float warp_sum(float v) {
#pragma unroll
    for (int o = 16; o; o >>= 1) v += __shfl_xor_sync(0xffffffffu, v, o);
    return v;
}

// Fused: layer1 (fan_in 1) -> relu -> BN -> layer2 (4x4 per-gene) -> relu -> BN
// One warp per gene (4 columns x 256 batch rows; 8 rows per lane). 8 genes/block.
__global__ __launch_bounds__(256) void k_layers12(
    const float* __restrict__ x,    // [BATCH, N_GENES] row-major
    const float* __restrict__ w1, const float* __restrict__ b1,
    const float* __restrict__ w2, const float* __restrict__ b2)
{
    __shared__ float sx[BATCH][GENES_PER_BLOCK + 1];

    const int g0 = blockIdx.x * GENES_PER_BLOCK;
    const int t = threadIdx.x;
    const int warp = t >> 5;
    const int lane = t & 31;

    // Load tile x[0:256, g0:g0+8]  (2048 elems, 8 per thread)
#pragma unroll
    for (int i = 0; i < 8; i++) {
        int elem = i * 256 + t;
        int r = elem >> 3;
        int c = elem & 7;
        sx[r][c] = x[r * N_GENES + g0 + c];
    }
    __syncthreads();

    const int gi = warp;           // one gene per warp
    const int g = g0 + gi;

    float w1v[4], b1v[4], b2v[4], w2v[16];
#pragma unroll
    for (int j = 0; j < 4; j++) {
        w1v[j] = w1[4 * g + j];
        b1v[j] = b1[4 * g + j];
        b2v[j] = b2[4 * g + j];
    }
#pragma unroll
    for (int e = 0; e < 16; e++) w2v[e] = w2[16 * g + e];

    // layer1 + relu ; lane handles batches b = lane + 32k
    float h1[8][4];
#pragma unroll
    for (int k = 0; k < 8; k++) {
        float xv = sx[lane + 32 * k][gi];
#pragma unroll
        for (int j = 0; j < 4; j++)
            h1[k][j] = fmaxf(fmaf(w1v[j], xv, b1v[j]), 0.0f);
    }

    // BatchNorm per column j (two-pass, warp-local)
#pragma unroll
    for (int j = 0; j < 4; j++) {
        float s = 0.f;
#pragma unroll
        for (int k = 0; k < 8; k++) s += h1[k][j];
        float m = warp_sum(s) * (1.0f / BATCH);
        float vs = 0.f;
#pragma unroll
        for (int k = 0; k < 8; k++) { float d = h1[k][j] - m; vs += d * d; }
        float inv = rsqrtf(warp_sum(vs) * (1.0f / BATCH) + EPS);
#pragma unroll
        for (int k = 0; k < 8; k++) h1[k][j] = (h1[k][j] - m) * inv;
    }

    // layer2 (4x4 dense per gene) + relu
    float h2[8][4];
#pragma unroll
    for (int k = 0; k < 8; k++) {
#pragma unroll
        for (int i = 0; i < 4; i++) {
            float acc = b2v[i];
#pragma unroll
            for (int j = 0; j < 4; j++) acc = fmaf(w2v[4 * i + j], h1[k][j], acc);
            h2[k][i] = fmaxf(acc, 0.0f);
        }
    }

    // BatchNorm per column i, then transposed fp16 store
#pragma unroll
    for (int i = 0; i < 4; i++) {
        float s = 0.f;
#pragma unroll
        for (int k = 0; k < 8; k++) s += h2[k][i];
        float m = warp_sum(s) * (1.0f / BATCH);
        float vs = 0.f;
#pragma unroll
        for (int k = 0; k < 8; k++) { float d = h2[k][i] - m; vs += d * d; }
        float inv = rsqrtf(warp_sum(vs) * (1.0f / BATCH) + EPS);
        __half* dst = &g_hT[(4 * g + i) * BATCH];
#pragma unroll
        for (int k = 0; k < 8; k++)
            dst[lane + 32 * k] = __float2half_rn((h2[k][i] - m) * inv);
    }
}

// layer3 gather + final BN. One block (128 threads) per TF; each thread owns
// two consecutive batch elements via __half2 loads.
__global__ __launch_bounds__(128) void k_layer3(
    const float* __restrict__ w3, const float* __restrict__ b3,
    const int* __restrict__ cols3,
    float* __restrict__ out)   // [BATCH, N_TF]
{
    const int tf = blockIdx.x;
    const int t = threadIdx.x;        // 0..127
    const int warp = t >> 5;
    const int lane = t & 31;

    __shared__ float sw[EDGES3];
    __shared__ int sc[EDGES3];
    __shared__ float sred[4];

    sw[t]       = w3[tf * EDGES3 + t];
    sw[t + 128] = w3[tf * EDGES3 + t + 128];
    sc[t]       = cols3[tf * EDGES3 + t] * BATCH;
    sc[t + 128] = cols3[tf * EDGES3 + t + 128] * BATCH;
    __syncthreads();

    float bias = b3[tf];
    float2 acc = make_float2(bias, bias);

#pragma unroll 16
    for (int e = 0; e < EDGES3; e++) {
        const __half2 hv = *reinterpret_cast<const __half2*>(&g_hT[sc[e] + 2 * t]);
        float2 f = __half22float2(hv);
        float w = sw[e];
        acc.x = fmaf(w, f.x, acc.x);
        acc.y = fmaf(w, f.y, acc.y);
    }

    // BN over 256 batch values (two-pass, block reduction over 4 warps)
    float s = warp_sum(acc.x + acc.y);
    if (lane == 0) sred[warp] = s;
    __syncthreads();
    float m = (sred[0] + sred[1] + sred[2] + sred[3]) * (1.0f / BATCH);
    __syncthreads();

    float dx = acc.x - m, dy = acc.y - m;
    float v = warp_sum(dx * dx + dy * dy);
    if (lane == 0) sred[warp] = v;
    __syncthreads();
    float var = (sred[0] + sred[1] + sred[2] + sred[3]) * (1.0f / BATCH);
    float inv = rsqrtf(var + EPS);

    out[(2 * t)     * N_TF + tf] = dx * inv;
    out[(2 * t + 1) * N_TF + tf] = dy * inv;
}

extern "C" void kernel_launch(void* const* d_in, const int* in_sizes, int n_in,
                              void* d_out, int out_size)
{
    const float* x  = (const float*)d_in[0];
    const float* w1 = (const float*)d_in[1];
    const float* b1 = (const float*)d_in[2];
    const float* w2 = (const float*)d_in[3];
    const float* b2 = (const float*)d_in[4];
    const float* w3 = (const float*)d_in[5];
    const float* b3 = (const float*)d_in[6];
    const int* cols3 = (const int*)d_in[12];
    float* out = (float*)d_out;

    k_layers12<<<N_GENES / GENES_PER_BLOCK, 256>>>(x, w1, b1, w2, b2);
    k_layer3<<<N_TF, 128>>>(w3, b3, cols3, out);
}